// round 7
// baseline (speedup 1.0000x reference)
#include <cuda_runtime.h>

// IFOPooling: h_t = f_t * h_{t-1} + i_t * z_t over the contiguous S axis.
// f,z,i: [B,H,S] fp32 (B=16,H=1024,S=2048). out: [B,H,S] fp32.
//
// Warp-autonomous: each warp owns one full row of 2048, processed as 8
// sequential chunks of 256 (8 elems/thread). Hidden state carried across
// chunks by a single lane-31 shuffle. No __syncthreads, no smem, no
// inter-warp coupling anywhere.

#define SEQ_LEN 2048
#define CHUNK   256
#define NCHUNK  (SEQ_LEN / CHUNK)   // 8
#define TPB     256
#define WPB     (TPB / 32)          // 8 rows per block

__global__ __launch_bounds__(TPB, 8) void ifo_warp_scan_kernel(
    const float* __restrict__ f,
    const float* __restrict__ z,
    const float* __restrict__ in_i,
    float* __restrict__ out,
    int rows)
{
    const int lane = threadIdx.x & 31;
    const int wid  = threadIdx.x >> 5;
    const int row  = blockIdx.x * WPB + wid;
    if (row >= rows) return;

    const unsigned mask = 0xffffffffu;
    const size_t base = (size_t)row * SEQ_LEN + (size_t)lane * 8;

    float h0 = 0.0f;   // hidden state entering the current chunk

#pragma unroll 1
    for (int c = 0; c < NCHUNK; c++) {
        const size_t off = base + (size_t)c * CHUNK;

        // ---- coalesced vectorized loads: warp covers 256 contiguous elems ----
        const float4 fA = *(const float4*)(f    + off);
        const float4 fB = *(const float4*)(f    + off + 4);
        const float4 zA = *(const float4*)(z    + off);
        const float4 zB = *(const float4*)(z    + off + 4);
        const float4 iA = *(const float4*)(in_i + off);
        const float4 iB = *(const float4*)(in_i + off + 4);

        float fv[8] = {fA.x, fA.y, fA.z, fA.w, fB.x, fB.y, fB.z, fB.w};
        float xv[8] = {iA.x * zA.x, iA.y * zA.y, iA.z * zA.z, iA.w * zA.w,
                       iB.x * zB.x, iB.y * zB.y, iB.z * zB.z, iB.w * zB.w};

        // ---- thread-local composition over 8 elems: h -> a*h + b ----
        float a = 1.0f, b = 0.0f;
#pragma unroll
        for (int k = 0; k < 8; k++) {
            a = fv[k] * a;
            b = fmaf(fv[k], b, xv[k]);
        }

        // ---- warp-inclusive scan of (a,b) via shuffles ----
        float ia = a, ib = b;
#pragma unroll
        for (int d = 1; d < 32; d <<= 1) {
            float pa = __shfl_up_sync(mask, ia, d);
            float pb = __shfl_up_sync(mask, ib, d);
            if (lane >= d) {
                ib = fmaf(ia, pb, ib);   // compose: prev then cur
                ia = ia * pa;
            }
        }
        // exclusive prefix for this thread
        float ea = __shfl_up_sync(mask, ia, 1);
        float eb = __shfl_up_sync(mask, ib, 1);
        if (lane == 0) { ea = 1.0f; eb = 0.0f; }

        // h entering this thread's 8-elem segment
        float h = fmaf(ea, h0, eb);

        // ---- replay local recurrence with true prefix ----
#pragma unroll
        for (int k = 0; k < 8; k++) {
            h = fmaf(fv[k], h, xv[k]);
            xv[k] = h;
        }

        // ---- coalesced vectorized stores ----
        *(float4*)(out + off)     = make_float4(xv[0], xv[1], xv[2], xv[3]);
        *(float4*)(out + off + 4) = make_float4(xv[4], xv[5], xv[6], xv[7]);

        // ---- carry hidden state to next chunk (lane 31's final h) ----
        h0 = __shfl_sync(mask, h, 31);
    }
}

extern "C" void kernel_launch(void* const* d_in, const int* in_sizes, int n_in,
                              void* d_out, int out_size)
{
    const float* f  = (const float*)d_in[0];
    const float* z  = (const float*)d_in[1];
    const float* ii = (const float*)d_in[2];
    float* out = (float*)d_out;

    const int rows = out_size / SEQ_LEN;          // B*H = 16384
    const int grid = (rows + WPB - 1) / WPB;      // 2048 blocks
    ifo_warp_scan_kernel<<<grid, TPB>>>(f, z, ii, out, rows);
}